// round 1
// baseline (speedup 1.0000x reference)
#include <cuda_runtime.h>
#include <math.h>

// Shapes (fixed by the problem)
#define Bsz   1024
#define Ssz   8
#define Hsz   16
#define DKsz  32
#define Dsz   512
#define MROWS (Bsz * Ssz)      // 8192
#define MASK_ELEMS (Bsz * Ssz * Ssz)  // 65536

// ---------------- scratch (static device globals: allocation-free) ----------
__device__ __align__(128) float g_q[MROWS * Dsz];
__device__ __align__(128) float g_k[MROWS * Dsz];
__device__ __align__(128) float g_v[MROWS * Dsz];
__device__ __align__(128) float g_ctx[MROWS * Dsz];
__device__ __align__(128) float g_pre[MROWS * Dsz];
__device__ int g_mask_mode;   // 0 = bool(1B), 1 = int32, 2 = float32

// ---------------- mask dtype probe ------------------------------------------
// We only ever read the first MASK_ELEMS bytes, which is in-bounds for every
// candidate dtype (>=1 byte/elem). Patterns:
//   float32 0/1.0f -> bytes in {0x00,0x80,0x3F}; any byte >= 2 => float32
//   int32   0/1    -> bytes in {0,1}, the 1s only at offset%4==0
//   bool           -> bytes in {0,1}, 1s at arbitrary offsets
__global__ void detect_mask_mode(const unsigned char* __restrict__ m) {
    __shared__ int s_ge2, s_odd1;
    if (threadIdx.x == 0) { s_ge2 = 0; s_odd1 = 0; }
    __syncthreads();
    int ge2 = 0, odd1 = 0;
    for (int i = threadIdx.x; i < MASK_ELEMS; i += blockDim.x) {
        unsigned char v = m[i];
        if (v >= 2) ge2 = 1;
        if (v == 1 && (i & 3)) odd1 = 1;
    }
    if (ge2)  atomicOr(&s_ge2, 1);
    if (odd1) atomicOr(&s_odd1, 1);
    __syncthreads();
    if (threadIdx.x == 0)
        g_mask_mode = s_ge2 ? 2 : (s_odd1 ? 0 : 1);
}

// ---------------- TN SGEMM: C[M,512] = A[M,512] @ W[512,512]^T + bias (+res)
#define BM 64
#define BN 64
#define BK 16

__global__ void __launch_bounds__(256)
gemm_tn(const float* __restrict__ A, const float* __restrict__ W,
        const float* __restrict__ bias, const float* __restrict__ resid,
        float* __restrict__ C)
{
    __shared__ __align__(16) float As[BK][BM];
    __shared__ __align__(16) float Bs[BK][BN];

    const int bn = blockIdx.x * BN;
    const int bm = blockIdx.y * BM;
    const int t  = threadIdx.x;
    const int tx = t & 15;          // n micro-tile index
    const int ty = t >> 4;          // m micro-tile index

    const int lrow = t >> 2;        // 0..63   (load row)
    const int lcol = (t & 3) * 4;   // 0,4,8,12 (load col group)

    float acc[4][4] = {};

    const float* aptr = A + (size_t)(bm + lrow) * Dsz + lcol;
    const float* bptr = W + (size_t)(bn + lrow) * Dsz + lcol;

    for (int k0 = 0; k0 < Dsz; k0 += BK) {
        float4 a4 = *(const float4*)(aptr + k0);
        float4 b4 = *(const float4*)(bptr + k0);
        As[lcol + 0][lrow] = a4.x; As[lcol + 1][lrow] = a4.y;
        As[lcol + 2][lrow] = a4.z; As[lcol + 3][lrow] = a4.w;
        Bs[lcol + 0][lrow] = b4.x; Bs[lcol + 1][lrow] = b4.y;
        Bs[lcol + 2][lrow] = b4.z; Bs[lcol + 3][lrow] = b4.w;
        __syncthreads();
#pragma unroll
        for (int k = 0; k < BK; k++) {
            float4 av = *(const float4*)(&As[k][ty * 4]);
            float4 bv = *(const float4*)(&Bs[k][tx * 4]);
            float a[4] = {av.x, av.y, av.z, av.w};
            float b[4] = {bv.x, bv.y, bv.z, bv.w};
#pragma unroll
            for (int i = 0; i < 4; i++)
#pragma unroll
                for (int j = 0; j < 4; j++)
                    acc[i][j] = fmaf(a[i], b[j], acc[i][j]);
        }
        __syncthreads();
    }

#pragma unroll
    for (int i = 0; i < 4; i++) {
        const int m = bm + ty * 4 + i;
#pragma unroll
        for (int j = 0; j < 4; j++) {
            const int n = bn + tx * 4 + j;
            float v = acc[i][j] + bias[n];
            if (resid) v += resid[(size_t)m * Dsz + n];
            C[(size_t)m * Dsz + n] = v;
        }
    }
}

// ---------------- attention: one block per (b, h), 64 threads ---------------
__global__ void __launch_bounds__(64)
attn_kernel(const void* __restrict__ maskp, const float* __restrict__ hyper,
            float* __restrict__ w_out)
{
    const int bh = blockIdx.x;
    const int b  = bh >> 4;
    const int h  = bh & 15;
    const int t  = threadIdx.x;

    __shared__ float qs[8][32], ks[8][32], vs[8][32], hy[8][32];
    __shared__ float sc[8][8], ws[8][8];

    const int base = (b * Ssz) * Dsz + h * DKsz;
    for (int idx = t; idx < 256; idx += 64) {
        const int i = idx >> 5, d = idx & 31;
        qs[i][d] = g_q[base + i * Dsz + d];
        ks[i][d] = g_k[base + i * Dsz + d];
        vs[i][d] = g_v[base + i * Dsz + d];
        hy[i][d] = hyper[b * (Hsz * Ssz * DKsz) + h * (Ssz * DKsz) + i * DKsz + d];
    }
    __syncthreads();

    const int i = t >> 3, j = t & 7;

    // mask lookup under detected dtype
    const int midx = b * 64 + i * 8 + j;
    const int mode = g_mask_mode;
    bool masked;
    if (mode == 0)      masked = ((const unsigned char*)maskp)[midx] != 0;
    else if (mode == 1) masked = ((const int*)maskp)[midx] != 0;
    else                masked = ((const float*)maskp)[midx] != 0.0f;

    float s;
    if (masked) {
        s = -1e9f;
    } else {
        float dot = 0.f;
#pragma unroll
        for (int d = 0; d < 32; d++) dot = fmaf(qs[i][d], ks[j][d], dot);
        s = dot * 0.17677669529663687f;   // 1/sqrt(32)
    }
    sc[i][j] = s;
    __syncthreads();

    // per-thread softmax over its row (redundant but trivially cheap)
    float mx = sc[i][0];
#pragma unroll
    for (int jj = 1; jj < 8; jj++) mx = fmaxf(mx, sc[i][jj]);
    float sum = 0.f;
#pragma unroll
    for (int jj = 0; jj < 8; jj++) sum += expf(sc[i][jj] - mx);
    const float w = expf(s - mx) / sum;
    ws[i][j] = w;
    w_out[(size_t)bh * 64 + i * 8 + j] = w;
    __syncthreads();

    // context: thread -> (row i, 4 consecutive d), gated by hyper
    const int d0 = (t & 7) * 4;
    float c0 = 0.f, c1 = 0.f, c2 = 0.f, c3 = 0.f;
#pragma unroll
    for (int jj = 0; jj < 8; jj++) {
        const float wv = ws[i][jj];
        c0 = fmaf(wv, vs[jj][d0 + 0], c0);
        c1 = fmaf(wv, vs[jj][d0 + 1], c1);
        c2 = fmaf(wv, vs[jj][d0 + 2], c2);
        c3 = fmaf(wv, vs[jj][d0 + 3], c3);
    }
    g_ctx[base + i * Dsz + d0 + 0] = c0 * hy[i][d0 + 0];
    g_ctx[base + i * Dsz + d0 + 1] = c1 * hy[i][d0 + 1];
    g_ctx[base + i * Dsz + d0 + 2] = c2 * hy[i][d0 + 2];
    g_ctx[base + i * Dsz + d0 + 3] = c3 * hy[i][d0 + 3];
}

// ---------------- layernorm: one warp per row of 512 ------------------------
__global__ void __launch_bounds__(256)
ln_kernel(const float* __restrict__ gamma, const float* __restrict__ beta,
          float* __restrict__ out)
{
    const int warp = (blockIdx.x * blockDim.x + threadIdx.x) >> 5;
    const int lane = threadIdx.x & 31;
    if (warp >= MROWS) return;
    const float* row = g_pre + (size_t)warp * Dsz;

    float x[16];
    float sum = 0.f, sumsq = 0.f;
#pragma unroll
    for (int i = 0; i < 16; i++) {
        x[i] = row[lane + i * 32];
        sum += x[i];
        sumsq = fmaf(x[i], x[i], sumsq);
    }
#pragma unroll
    for (int o = 16; o > 0; o >>= 1) {
        sum   += __shfl_xor_sync(0xFFFFFFFFu, sum, o);
        sumsq += __shfl_xor_sync(0xFFFFFFFFu, sumsq, o);
    }
    const float mu  = sum * (1.0f / 512.0f);
    const float var = sumsq * (1.0f / 512.0f) - mu * mu;
    const float rs  = rsqrtf(var + 1e-5f);
#pragma unroll
    for (int i = 0; i < 16; i++) {
        const int c = lane + i * 32;
        out[(size_t)warp * Dsz + c] = (x[i] - mu) * rs * gamma[c] + beta[c];
    }
}

// ---------------- launcher ---------------------------------------------------
extern "C" void kernel_launch(void* const* d_in, const int* in_sizes, int n_in,
                              void* d_out, int out_size)
{
    const float* Q     = (const float*)d_in[0];
    const float* K     = (const float*)d_in[1];
    const float* V     = (const float*)d_in[2];
    const void*  mask  = d_in[3];
    const float* hyper = (const float*)d_in[4];
    const float* Wq    = (const float*)d_in[5];
    const float* bq    = (const float*)d_in[6];
    const float* Wk    = (const float*)d_in[7];
    const float* bk    = (const float*)d_in[8];
    const float* Wv    = (const float*)d_in[9];
    const float* bv    = (const float*)d_in[10];
    const float* Wo    = (const float*)d_in[11];
    const float* bo    = (const float*)d_in[12];
    const float* ln_g  = (const float*)d_in[13];
    const float* ln_b  = (const float*)d_in[14];

    float* out   = (float*)d_out;
    float* w_out = out + (size_t)MROWS * Dsz;   // weights section of output

    float *gq, *gk, *gv, *gctx, *gpre;
    cudaGetSymbolAddress((void**)&gq,   g_q);
    cudaGetSymbolAddress((void**)&gk,   g_k);
    cudaGetSymbolAddress((void**)&gv,   g_v);
    cudaGetSymbolAddress((void**)&gctx, g_ctx);
    cudaGetSymbolAddress((void**)&gpre, g_pre);

    detect_mask_mode<<<1, 256>>>((const unsigned char*)mask);

    dim3 gg(Dsz / BN, MROWS / BM);   // (8, 128)
    gemm_tn<<<gg, 256>>>(Q, Wq, bq, nullptr, gq);
    gemm_tn<<<gg, 256>>>(K, Wk, bk, nullptr, gk);
    gemm_tn<<<gg, 256>>>(V, Wv, bv, nullptr, gv);

    attn_kernel<<<Bsz * Hsz, 64>>>(mask, hyper, w_out);

    gemm_tn<<<gg, 256>>>(gctx, Wo, bo, Q, gpre);

    ln_kernel<<<(MROWS * 32 + 255) / 256, 256>>>(ln_g, ln_b, out);
}

// round 4
// speedup vs baseline: 2.1499x; 2.1499x over previous
#include <cuda_runtime.h>
#include <cuda_bf16.h>
#include <cstdint>
#include <math.h>

// Shapes (fixed by the problem)
#define Bsz   1024
#define Ssz   8
#define Hsz   16
#define DKsz  32
#define Dsz   512
#define MROWS (Bsz * Ssz)              // 8192
#define MASK_ELEMS (Bsz * Ssz * Ssz)   // 65536
#define KP    1536                      // split-expanded K (3 * 512)
#define NITER 48                        // KP / 32

// GEMM tiling
#define BM 128
#define BN 128
#define BK 32
#define STAGES 3
#define ROWB 80                         // smem row stride bytes (64B data + 16B skew)
#define ASTG (128 * ROWB)               // 10240 B
#define STG  (2 * ASTG)                 // 20480 B per stage
#define GEMM_SMEM (STAGES * STG)        // 61440 B

// ---------------- scratch (static device globals: allocation-free) ----------
__device__ __align__(128) float g_q[MROWS * Dsz];
__device__ __align__(128) float g_k[MROWS * Dsz];
__device__ __align__(128) float g_v[MROWS * Dsz];
__device__ __align__(128) float g_pre[MROWS * Dsz];
__device__ __align__(128) __nv_bfloat16 g_aq[MROWS * KP];
__device__ __align__(128) __nv_bfloat16 g_ak[MROWS * KP];
__device__ __align__(128) __nv_bfloat16 g_av[MROWS * KP];
__device__ __align__(128) __nv_bfloat16 g_actx[MROWS * KP];
__device__ __align__(128) __nv_bfloat16 g_wq[Dsz * KP];
__device__ __align__(128) __nv_bfloat16 g_wk[Dsz * KP];
__device__ __align__(128) __nv_bfloat16 g_wv[Dsz * KP];
__device__ __align__(128) __nv_bfloat16 g_wo[Dsz * KP];
__device__ int g_mask_mode;   // 0 = bool(1B), 1 = int32, 2 = float32

// ---------------- PTX helpers (ALL baseline sm_80/sm_90 — no 'a' features) --
__device__ __forceinline__ uint32_t smem_to_u32(const void* p) {
    uint32_t a;
    asm("{ .reg .u64 t; cvta.to.shared.u64 t, %1; cvt.u32.u64 %0, t; }"
        : "=r"(a) : "l"(p));
    return a;
}
#define CP_ASYNC16(dst, src) \
    asm volatile("cp.async.cg.shared.global [%0], [%1], 16;" \
        :: "r"(dst), "l"(src))
#define CP_COMMIT() asm volatile("cp.async.commit_group;" ::: "memory")
#define CP_WAIT1()  asm volatile("cp.async.wait_group 1;" ::: "memory")

__device__ __forceinline__ void ldsm4(uint32_t r[4], uint32_t addr) {
    asm volatile("ldmatrix.sync.aligned.m8n8.x4.shared.b16 {%0,%1,%2,%3}, [%4];"
        : "=r"(r[0]), "=r"(r[1]), "=r"(r[2]), "=r"(r[3]) : "r"(addr));
}
__device__ __forceinline__ void mma16816(float c[4], const uint32_t a[4],
                                         const uint32_t b[2]) {
    asm volatile(
        "mma.sync.aligned.m16n8k16.row.col.f32.bf16.bf16.f32 "
        "{%0,%1,%2,%3}, {%4,%5,%6,%7}, {%8,%9}, {%0,%1,%2,%3};"
        : "+f"(c[0]), "+f"(c[1]), "+f"(c[2]), "+f"(c[3])
        : "r"(a[0]), "r"(a[1]), "r"(a[2]), "r"(a[3]), "r"(b[0]), "r"(b[1]));
}

// ---------------- mask dtype probe (single block, deterministic) -------------
__global__ void __launch_bounds__(256)
detect_mask(const unsigned char* __restrict__ m) {
    int ge2 = 0, odd1 = 0;
    for (int i = threadIdx.x; i < MASK_ELEMS; i += 256) {
        unsigned char v = m[i];
        if (v >= 2) ge2 = 1;
        if (v == 1 && (i & 3)) odd1 = 1;
    }
    ge2  = __syncthreads_or(ge2);
    odd1 = __syncthreads_or(odd1);
    if (threadIdx.x == 0)
        g_mask_mode = ge2 ? 2 : (odd1 ? 0 : 1);
}

// ---------------- fp32 -> split-bf16: [rows,512] -> [rows,1536] --------------
// A-side (wside=0): [hi | lo | hi]   W-side (wside=1): [hi | hi | lo]
// A'.W' = a_hi.w_hi + a_lo.w_hi + a_hi.w_lo  ~= a.w  (err ~2^-16)
__global__ void __launch_bounds__(256)
split_kernel(const float* __restrict__ in, __nv_bfloat16* __restrict__ out,
             int rows, int wside)
{
    int idx = (blockIdx.x * 256 + threadIdx.x) * 4;
    if (idx >= rows * Dsz) return;
    int r = idx >> 9;
    int k = idx & 511;
    float4 v = *(const float4*)(in + idx);

    __nv_bfloat16 h0 = __float2bfloat16_rn(v.x);
    __nv_bfloat16 h1 = __float2bfloat16_rn(v.y);
    __nv_bfloat16 h2 = __float2bfloat16_rn(v.z);
    __nv_bfloat16 h3 = __float2bfloat16_rn(v.w);
    __nv_bfloat16 l0 = __float2bfloat16_rn(v.x - __bfloat162float(h0));
    __nv_bfloat16 l1 = __float2bfloat16_rn(v.y - __bfloat162float(h1));
    __nv_bfloat16 l2 = __float2bfloat16_rn(v.z - __bfloat162float(h2));
    __nv_bfloat16 l3 = __float2bfloat16_rn(v.w - __bfloat162float(h3));

    __nv_bfloat16* rowp = out + (size_t)r * KP;
    __nv_bfloat162 hA = {h0, h1}, hB = {h2, h3};
    __nv_bfloat162 lA = {l0, l1}, lB = {l2, l3};
    const int mid = wside ? 1024 : 512;    // where lo goes
    const int dup = wside ? 512  : 1024;   // where hi duplicate goes
    *(__nv_bfloat162*)(rowp + k)           = hA;
    *(__nv_bfloat162*)(rowp + k + 2)       = hB;
    *(__nv_bfloat162*)(rowp + mid + k)     = lA;
    *(__nv_bfloat162*)(rowp + mid + k + 2) = lB;
    *(__nv_bfloat162*)(rowp + dup + k)     = hA;
    *(__nv_bfloat162*)(rowp + dup + k + 2) = hB;
}

// ---------------- bf16 mma.sync GEMM: C[M,512] = A'[M,1536] @ W'[512,1536]^T
// 128x128 CTA tile, 8 warps (warp tile 64x32), BK=32, 3-stage cp.async.
__global__ void __launch_bounds__(256)
gemm_mma(const __nv_bfloat16* __restrict__ A, const __nv_bfloat16* __restrict__ W,
         const float* __restrict__ bias, const float* __restrict__ resid,
         float* __restrict__ C)
{
    extern __shared__ __align__(16) char sm[];
    const uint32_t smb = smem_to_u32(sm);

    const int t    = threadIdx.x;
    const int lane = t & 31;
    const int wid  = t >> 5;
    const int wm   = (wid & 1) * 64;        // warp m offset
    const int wn   = (wid >> 1) * 32;       // warp n offset
    const int bm   = blockIdx.y * BM;
    const int bn   = blockIdx.x * BN;

    // ldmatrix smem offsets (relative to stage base)
    // A: matrices [rows0-7,k0-7][rows8-15,k0-7][rows0-7,k8-15][rows8-15,k8-15]
    uint32_t aOff[4], bOff[2];
    {
        const int ar = (lane & 15);
        const int ag = (lane >> 4) & 1;
#pragma unroll
        for (int mt = 0; mt < 4; mt++)
            aOff[mt] = (uint32_t)((wm + mt * 16 + ar) * ROWB + ag * 16);
        const int br = (lane & 7) + ((lane & 16) >> 1);
        const int bg = (lane >> 3) & 1;
#pragma unroll
        for (int p = 0; p < 2; p++)
            bOff[p] = (uint32_t)(ASTG + (wn + p * 16 + br) * ROWB + bg * 16);
    }

    // cp.async coordinates: 512 granules (128 rows x 4 x 16B) per operand
    int lr[2], lg[2];
    uint32_t lso[2];
#pragma unroll
    for (int j = 0; j < 2; j++) {
        const int id = t + j * 256;         // 0..511
        lr[j] = id >> 2;
        lg[j] = id & 3;
        lso[j] = (uint32_t)(lr[j] * ROWB + lg[j] * 16);
    }
    const char* Ab = (const char*)(A + (size_t)bm * KP);
    const char* Wb = (const char*)(W + (size_t)bn * KP);

    // issue loads for one stage
    auto issue = [&](int stage, int kiter) {
        const uint32_t sb = smb + (stage) * STG;
        const int kb = kiter * (BK * 2);    // byte offset along K
#pragma unroll
        for (int j = 0; j < 2; j++) {
            CP_ASYNC16(sb + lso[j],        Ab + (size_t)lr[j] * (KP * 2) + kb + lg[j] * 16);
            CP_ASYNC16(sb + ASTG + lso[j], Wb + (size_t)lr[j] * (KP * 2) + kb + lg[j] * 16);
        }
    };

    float c[4][4][4];
#pragma unroll
    for (int mt = 0; mt < 4; mt++)
#pragma unroll
        for (int nt = 0; nt < 4; nt++)
#pragma unroll
            for (int q = 0; q < 4; q++) c[mt][nt][q] = 0.f;

    issue(0, 0); CP_COMMIT();
    issue(1, 1); CP_COMMIT();

    int st = 0;
    for (int j = 0; j < NITER; j++) {
        CP_WAIT1();
        __syncthreads();

        if (j + 2 < NITER) issue((st + 2) % STAGES, j + 2);
        CP_COMMIT();

        const uint32_t sb = smb + st * STG;
#pragma unroll
        for (int s = 0; s < 2; s++) {       // two k16 steps per BK=32
            uint32_t af[4][4], bf[4][2];
#pragma unroll
            for (int mt = 0; mt < 4; mt++)
                ldsm4(af[mt], sb + aOff[mt] + s * 32);
#pragma unroll
            for (int p = 0; p < 2; p++) {
                uint32_t r[4];
                ldsm4(r, sb + bOff[p] + s * 32);
                bf[2 * p][0]     = r[0]; bf[2 * p][1]     = r[1];
                bf[2 * p + 1][0] = r[2]; bf[2 * p + 1][1] = r[3];
            }
#pragma unroll
            for (int mt = 0; mt < 4; mt++)
#pragma unroll
                for (int nt = 0; nt < 4; nt++)
                    mma16816(c[mt][nt], af[mt], bf[nt]);
        }
        __syncthreads();
        st = (st + 1) % STAGES;
    }

    // epilogue: bias (+residual) fused
    const int rq = lane >> 2;               // 0..7
    const int cq = (lane & 3) * 2;          // 0,2,4,6
#pragma unroll
    for (int mt = 0; mt < 4; mt++) {
        const int r0 = bm + wm + mt * 16 + rq;
#pragma unroll
        for (int nt = 0; nt < 4; nt++) {
            const int col = bn + wn + nt * 8 + cq;
            float2 bia = *(const float2*)(bias + col);
            float2 v0 = {c[mt][nt][0] + bia.x, c[mt][nt][1] + bia.y};
            float2 v1 = {c[mt][nt][2] + bia.x, c[mt][nt][3] + bia.y};
            if (resid) {
                float2 e0 = *(const float2*)(resid + (size_t)r0 * Dsz + col);
                float2 e1 = *(const float2*)(resid + (size_t)(r0 + 8) * Dsz + col);
                v0.x += e0.x; v0.y += e0.y;
                v1.x += e1.x; v1.y += e1.y;
            }
            *(float2*)(C + (size_t)r0 * Dsz + col)       = v0;
            *(float2*)(C + (size_t)(r0 + 8) * Dsz + col) = v1;
        }
    }
}

// ---------------- attention: one block per (b, h), 64 threads ---------------
// Writes softmax weights and split-bf16 gated context (A-side layout).
__global__ void __launch_bounds__(64)
attn_kernel(const void* __restrict__ maskp, const float* __restrict__ hyper,
            float* __restrict__ w_out)
{
    const int bh = blockIdx.x;
    const int b  = bh >> 4;
    const int h  = bh & 15;
    const int t  = threadIdx.x;

    __shared__ float qs[8][32], ks[8][32], vs[8][32], hy[8][32];
    __shared__ float sc[8][8], ws[8][8];

    const int base = (b * Ssz) * Dsz + h * DKsz;
    for (int idx = t; idx < 256; idx += 64) {
        const int i = idx >> 5, d = idx & 31;
        qs[i][d] = g_q[base + i * Dsz + d];
        ks[i][d] = g_k[base + i * Dsz + d];
        vs[i][d] = g_v[base + i * Dsz + d];
        hy[i][d] = hyper[b * (Hsz * Ssz * DKsz) + h * (Ssz * DKsz) + i * DKsz + d];
    }
    __syncthreads();

    const int i = t >> 3, j = t & 7;

    const int midx = b * 64 + i * 8 + j;
    const int mode = g_mask_mode;
    bool masked;
    if (mode == 0)      masked = ((const unsigned char*)maskp)[midx] != 0;
    else if (mode == 1) masked = ((const int*)maskp)[midx] != 0;
    else                masked = ((const float*)maskp)[midx] != 0.0f;

    float s;
    if (masked) {
        s = -1e9f;
    } else {
        float dot = 0.f;
#pragma unroll
        for (int d = 0; d < 32; d++) dot = fmaf(qs[i][d], ks[j][d], dot);
        s = dot * 0.17677669529663687f;   // 1/sqrt(32)
    }
    sc[i][j] = s;
    __syncthreads();

    float mx = sc[i][0];
#pragma unroll
    for (int jj = 1; jj < 8; jj++) mx = fmaxf(mx, sc[i][jj]);
    float sum = 0.f;
#pragma unroll
    for (int jj = 0; jj < 8; jj++) sum += expf(sc[i][jj] - mx);
    const float w = expf(s - mx) / sum;
    ws[i][j] = w;
    w_out[(size_t)bh * 64 + i * 8 + j] = w;
    __syncthreads();

    // context row i, 4 consecutive d; gate by hyper; emit A-side split triple
    const int d0 = (t & 7) * 4;
    float c[4] = {};
#pragma unroll
    for (int jj = 0; jj < 8; jj++) {
        const float wv = ws[i][jj];
#pragma unroll
        for (int q = 0; q < 4; q++) c[q] = fmaf(wv, vs[jj][d0 + q], c[q]);
    }
    const int row = b * Ssz + i;
    const int k0  = h * DKsz + d0;              // col in [0,512)
    __nv_bfloat16* rowp = g_actx + (size_t)row * KP;
    __nv_bfloat16 hi[4], lo[4];
#pragma unroll
    for (int q = 0; q < 4; q++) {
        const float val = c[q] * hy[i][d0 + q];
        hi[q] = __float2bfloat16_rn(val);
        lo[q] = __float2bfloat16_rn(val - __bfloat162float(hi[q]));
    }
    __nv_bfloat162 hA = {hi[0], hi[1]}, hB = {hi[2], hi[3]};
    __nv_bfloat162 lA = {lo[0], lo[1]}, lB = {lo[2], lo[3]};
    *(__nv_bfloat162*)(rowp + k0)            = hA;   // hi
    *(__nv_bfloat162*)(rowp + k0 + 2)        = hB;
    *(__nv_bfloat162*)(rowp + 512 + k0)      = lA;   // lo
    *(__nv_bfloat162*)(rowp + 512 + k0 + 2)  = lB;
    *(__nv_bfloat162*)(rowp + 1024 + k0)     = hA;   // hi dup
    *(__nv_bfloat162*)(rowp + 1024 + k0 + 2) = hB;
}

// ---------------- layernorm: one warp per row of 512 ------------------------
__global__ void __launch_bounds__(256)
ln_kernel(const float* __restrict__ gamma, const float* __restrict__ beta,
          float* __restrict__ out)
{
    const int warp = (blockIdx.x * blockDim.x + threadIdx.x) >> 5;
    const int lane = threadIdx.x & 31;
    if (warp >= MROWS) return;
    const float* row = g_pre + (size_t)warp * Dsz;

    float x[16];
    float sum = 0.f, sumsq = 0.f;
#pragma unroll
    for (int i = 0; i < 16; i++) {
        x[i] = row[lane + i * 32];
        sum += x[i];
        sumsq = fmaf(x[i], x[i], sumsq);
    }
#pragma unroll
    for (int o = 16; o > 0; o >>= 1) {
        sum   += __shfl_xor_sync(0xFFFFFFFFu, sum, o);
        sumsq += __shfl_xor_sync(0xFFFFFFFFu, sumsq, o);
    }
    const float mu  = sum * (1.0f / 512.0f);
    const float var = sumsq * (1.0f / 512.0f) - mu * mu;
    const float rs  = rsqrtf(var + 1e-5f);
#pragma unroll
    for (int i = 0; i < 16; i++) {
        const int c = lane + i * 32;
        out[(size_t)warp * Dsz + c] = (x[i] - mu) * rs * gamma[c] + beta[c];
    }
}

// ---------------- launcher ---------------------------------------------------
extern "C" void kernel_launch(void* const* d_in, const int* in_sizes, int n_in,
                              void* d_out, int out_size)
{
    const float* Q     = (const float*)d_in[0];
    const float* K     = (const float*)d_in[1];
    const float* V     = (const float*)d_in[2];
    const void*  mask  = d_in[3];
    const float* hyper = (const float*)d_in[4];
    const float* Wq    = (const float*)d_in[5];
    const float* bq    = (const float*)d_in[6];
    const float* Wk    = (const float*)d_in[7];
    const float* bk    = (const float*)d_in[8];
    const float* Wv    = (const float*)d_in[9];
    const float* bv    = (const float*)d_in[10];
    const float* Wo    = (const float*)d_in[11];
    const float* bo    = (const float*)d_in[12];
    const float* ln_g  = (const float*)d_in[13];
    const float* ln_b  = (const float*)d_in[14];

    float* out   = (float*)d_out;
    float* w_out = out + (size_t)MROWS * Dsz;

    float *gq, *gk, *gv, *gpre;
    __nv_bfloat16 *aq, *ak, *av, *actx, *wqp, *wkp, *wvp, *wop;
    cudaGetSymbolAddress((void**)&gq,   g_q);
    cudaGetSymbolAddress((void**)&gk,   g_k);
    cudaGetSymbolAddress((void**)&gv,   g_v);
    cudaGetSymbolAddress((void**)&gpre, g_pre);
    cudaGetSymbolAddress((void**)&aq,   g_aq);
    cudaGetSymbolAddress((void**)&ak,   g_ak);
    cudaGetSymbolAddress((void**)&av,   g_av);
    cudaGetSymbolAddress((void**)&actx, g_actx);
    cudaGetSymbolAddress((void**)&wqp,  g_wq);
    cudaGetSymbolAddress((void**)&wkp,  g_wk);
    cudaGetSymbolAddress((void**)&wvp,  g_wv);
    cudaGetSymbolAddress((void**)&wop,  g_wo);

    cudaFuncSetAttribute(gemm_mma, cudaFuncAttributeMaxDynamicSharedMemorySize, GEMM_SMEM);

    // mask dtype probe
    detect_mask<<<1, 256>>>((const unsigned char*)mask);

    // fp32 -> split-bf16 converts (A-side vs W-side layouts differ!)
    const int big_blocks   = (MROWS * Dsz / 4 + 255) / 256;  // 4096
    const int small_blocks = (Dsz * Dsz / 4 + 255) / 256;    // 256
    split_kernel<<<big_blocks, 256>>>(Q,  aq,  MROWS, 0);
    split_kernel<<<big_blocks, 256>>>(K,  ak,  MROWS, 0);
    split_kernel<<<big_blocks, 256>>>(V,  av,  MROWS, 0);
    split_kernel<<<small_blocks, 256>>>(Wq, wqp, Dsz, 1);
    split_kernel<<<small_blocks, 256>>>(Wk, wkp, Dsz, 1);
    split_kernel<<<small_blocks, 256>>>(Wv, wvp, Dsz, 1);
    split_kernel<<<small_blocks, 256>>>(Wo, wop, Dsz, 1);

    // projections (tensor-core mma.sync)
    dim3 gg(Dsz / BN, MROWS / BM);   // (4, 64)
    gemm_mma<<<gg, 256, GEMM_SMEM>>>(aq, wqp, bq, nullptr, gq);
    gemm_mma<<<gg, 256, GEMM_SMEM>>>(ak, wkp, bk, nullptr, gk);
    gemm_mma<<<gg, 256, GEMM_SMEM>>>(av, wvp, bv, nullptr, gv);

    // attention (emits weights + split-bf16 gated context)
    attn_kernel<<<Bsz * Hsz, 64>>>(mask, hyper, w_out);

    // output projection with fused residual (tensor-core mma.sync)
    gemm_mma<<<gg, 256, GEMM_SMEM>>>(actx, wop, bo, Q, gpre);

    // layernorm
    ln_kernel<<<(MROWS * 32 + 255) / 256, 256>>>(ln_g, ln_b, out);
}

// round 5
// speedup vs baseline: 2.8978x; 1.3479x over previous
#include <cuda_runtime.h>
#include <cuda_fp16.h>
#include <cstdint>
#include <math.h>

// Shapes (fixed by the problem)
#define Bsz   1024
#define Ssz   8
#define Hsz   16
#define Dsz   512
#define MROWS 8192
#define MASK_ELEMS 65536
#define KP    1024                      // 2-term split K (2 * 512)
#define NITER 32                        // KP / 32

// GEMM tiling
#define BM 128
#define BN 128
#define BK 32
#define STAGES 4
#define ROWB 80                         // smem row stride (64B data + 16B skew)
#define ASTG (128 * ROWB)               // 10240 B
#define STG  (2 * ASTG)                 // 20480 B per stage
#define GEMM_SMEM (STAGES * STG)        // 81920 B

// ---------------- scratch (static device globals: allocation-free) ----------
__device__ __align__(128) float g_qkv[MROWS * 1536];      // q|k|v projections
__device__ __align__(128) float g_pre[MROWS * Dsz];
__device__ __align__(128) __half g_aq[MROWS * KP];
__device__ __align__(128) __half g_ak[MROWS * KP];
__device__ __align__(128) __half g_av[MROWS * KP];
__device__ __align__(128) __half g_actx[MROWS * KP];
__device__ __align__(128) __half g_wqkv[1536 * 512];      // fp16 hi of Wq|Wk|Wv
__device__ __align__(128) __half g_wo[512 * 512];         // fp16 hi of Wo
__device__ __align__(128) float g_bqkv[1536];
__device__ int g_mask_mode;   // 0 = bool(1B), 1 = int32, 2 = float32

// ---------------- PTX helpers (baseline sm_80/90 — no 'a' features) ---------
__device__ __forceinline__ uint32_t smem_to_u32(const void* p) {
    uint32_t a;
    asm("{ .reg .u64 t; cvta.to.shared.u64 t, %1; cvt.u32.u64 %0, t; }"
        : "=r"(a) : "l"(p));
    return a;
}
#define CP_ASYNC16(dst, src) \
    asm volatile("cp.async.cg.shared.global [%0], [%1], 16;" :: "r"(dst), "l"(src))
#define CP_COMMIT() asm volatile("cp.async.commit_group;" ::: "memory")
#define CP_WAIT2()  asm volatile("cp.async.wait_group 2;" ::: "memory")

__device__ __forceinline__ void ldsm4(uint32_t r[4], uint32_t addr) {
    asm volatile("ldmatrix.sync.aligned.m8n8.x4.shared.b16 {%0,%1,%2,%3}, [%4];"
        : "=r"(r[0]), "=r"(r[1]), "=r"(r[2]), "=r"(r[3]) : "r"(addr));
}
__device__ __forceinline__ void mma16816(float c[4], const uint32_t a[4],
                                         const uint32_t b[2]) {
    asm volatile(
        "mma.sync.aligned.m16n8k16.row.col.f32.f16.f16.f32 "
        "{%0,%1,%2,%3}, {%4,%5,%6,%7}, {%8,%9}, {%0,%1,%2,%3};"
        : "+f"(c[0]), "+f"(c[1]), "+f"(c[2]), "+f"(c[3])
        : "r"(a[0]), "r"(a[1]), "r"(a[2]), "r"(a[3]), "r"(b[0]), "r"(b[1]));
}

// ---------------- mask dtype probe (single block, vectorized) ----------------
__global__ void __launch_bounds__(256)
detect_mask(const uint4* __restrict__ m4) {
    uint32_t ge2 = 0, odd = 0;
    for (int i = threadIdx.x; i < MASK_ELEMS / 16; i += 256) {
        uint4 w = m4[i];
        const uint32_t a = w.x | w.y | w.z | w.w;
        ge2 |= (a & 0xFEFEFEFEu);
        odd |= (a & 0xFFFFFF00u);
    }
    ge2 = __syncthreads_or((int)(ge2 != 0));
    odd = __syncthreads_or((int)(odd != 0));
    if (threadIdx.x == 0)
        g_mask_mode = ge2 ? 2 : (odd ? 0 : 1);
}

// ---------------- bias concat: [bq|bk|bv] -> g_bqkv --------------------------
__global__ void __launch_bounds__(256)
concat_bias(const float* __restrict__ bq, const float* __restrict__ bk,
            const float* __restrict__ bv) {
    const int i = blockIdx.x * 256 + threadIdx.x;
    if (i < 1536)
        g_bqkv[i] = i < 512 ? bq[i] : (i < 1024 ? bk[i - 512] : bv[i - 1024]);
}

// ---------------- fp32 -> [hi|lo] fp16 split: [8192,512] -> [8192,1024] ------
// grid.z selects Q/K/V.  hi = fp16(v); lo = fp16(v - hi).
__global__ void __launch_bounds__(256)
split_a(const float* __restrict__ Q, const float* __restrict__ K,
        const float* __restrict__ V, __half* __restrict__ oq,
        __half* __restrict__ ok, __half* __restrict__ ov)
{
    const int z = blockIdx.z;
    const float* in = z == 0 ? Q : (z == 1 ? K : V);
    __half* out     = z == 0 ? oq : (z == 1 ? ok : ov);
    const int idx = (blockIdx.x * 256 + threadIdx.x) * 4;
    const int r = idx >> 9, k = idx & 511;
    float4 v = *(const float4*)(in + idx);

    __half h0 = __float2half_rn(v.x), h1 = __float2half_rn(v.y);
    __half h2 = __float2half_rn(v.z), h3 = __float2half_rn(v.w);
    __half l0 = __float2half_rn(v.x - __half2float(h0));
    __half l1 = __float2half_rn(v.y - __half2float(h1));
    __half l2 = __float2half_rn(v.z - __half2float(h2));
    __half l3 = __float2half_rn(v.w - __half2float(h3));

    __half* rowp = out + (size_t)r * KP;
    *(__half2*)(rowp + k)           = {h0, h1};
    *(__half2*)(rowp + k + 2)       = {h2, h3};
    *(__half2*)(rowp + 512 + k)     = {l0, l1};
    *(__half2*)(rowp + 512 + k + 2) = {l2, l3};
}

// ---------------- weight fp32 -> fp16 hi only: [512,512] ---------------------
// grid.z: 0..2 -> g_wqkv sections, 3 -> g_wo
__global__ void __launch_bounds__(256)
conv_w(const float* __restrict__ Wq, const float* __restrict__ Wk,
       const float* __restrict__ Wv, const float* __restrict__ Wo)
{
    const int z = blockIdx.z;
    const float* in = z == 0 ? Wq : (z == 1 ? Wk : (z == 2 ? Wv : Wo));
    __half* out = z < 3 ? (g_wqkv + (size_t)z * 512 * 512) : g_wo;
    const int idx = (blockIdx.x * 256 + threadIdx.x) * 4;
    float4 v = *(const float4*)(in + idx);
    *(__half2*)(out + idx)     = {__float2half_rn(v.x), __float2half_rn(v.y)};
    *(__half2*)(out + idx + 2) = {__float2half_rn(v.z), __float2half_rn(v.w)};
}

// ---------------- fp16 mma.sync GEMM --------------------------------------
// C[m, col] = A'[m, 0:1024] @ Whi[col, 0:512]^T  with K schedule:
//   iters 0-15:  A hi section    x W rows    (hi.hi)
//   iters 16-31: A lo section    x W rows    (lo.hi)
// 128x128 CTA tile, 8 warps (warp tile 64x32), BK=32, 4-stage cp.async,
// ONE __syncthreads per iter.  QKV variant: grid.z selects input matrix and
// weight section; output column base = z*512.
template<bool QKV>
__global__ void __launch_bounds__(256)
gemm_mma(const __half* __restrict__ A0, const __half* __restrict__ A1,
         const __half* __restrict__ A2, const __half* __restrict__ Wp,
         const float* __restrict__ bias, const float* __restrict__ resid,
         float* __restrict__ C)
{
    const int ldc = QKV ? 1536 : 512;
    extern __shared__ __align__(16) char sm[];
    const uint32_t smb = smem_to_u32(sm);

    const int t    = threadIdx.x;
    const int lane = t & 31;
    const int wid  = t >> 5;
    const int wm   = (wid & 1) * 64;
    const int wn   = (wid >> 1) * 32;
    const int bm   = blockIdx.y * BM;
    const int z    = QKV ? blockIdx.z : 0;
    const int colbase = z * 512 + blockIdx.x * BN;

    const __half* A = QKV ? (z == 0 ? A0 : (z == 1 ? A1 : A2)) : A0;
    const __half* W = QKV ? (Wp + (size_t)z * 512 * 512) : Wp;

    // ldmatrix smem offsets (relative to stage base)
    uint32_t aOff[4], bOff[2];
    {
        const int ar = (lane & 15);
        const int ag = (lane >> 4) & 1;
#pragma unroll
        for (int mt = 0; mt < 4; mt++)
            aOff[mt] = (uint32_t)((wm + mt * 16 + ar) * ROWB + ag * 16);
        const int br = (lane & 7) + ((lane & 16) >> 1);
        const int bg = (lane >> 3) & 1;
#pragma unroll
        for (int p = 0; p < 2; p++)
            bOff[p] = (uint32_t)(ASTG + (wn + p * 16 + br) * ROWB + bg * 16);
    }

    // cp.async coordinates: 512 granules (128 rows x 4 x 16B) per operand
    int lr[2], lg[2];
    uint32_t lso[2];
#pragma unroll
    for (int j = 0; j < 2; j++) {
        const int id = t + j * 256;
        lr[j] = id >> 2;
        lg[j] = id & 3;
        lso[j] = (uint32_t)(lr[j] * ROWB + lg[j] * 16);
    }
    const char* Ab = (const char*)(A + (size_t)bm * KP);              // 2048 B/row
    const char* Wb = (const char*)(W + (size_t)(blockIdx.x * BN) * 512); // 1024 B/row

    auto issue = [&](int stage, int j) {
        const uint32_t sb = smb + stage * STG;
        const int kbA = j * 64;          // A: sequential through [hi|lo]
        const int kbW = (j & 15) * 64;   // W: hi twice
#pragma unroll
        for (int jj = 0; jj < 2; jj++) {
            CP_ASYNC16(sb + lso[jj],        Ab + (size_t)lr[jj] * 2048 + kbA + lg[jj] * 16);
            CP_ASYNC16(sb + ASTG + lso[jj], Wb + (size_t)lr[jj] * 1024 + kbW + lg[jj] * 16);
        }
    };

    float c[4][4][4];
#pragma unroll
    for (int mt = 0; mt < 4; mt++)
#pragma unroll
        for (int nt = 0; nt < 4; nt++)
#pragma unroll
            for (int q = 0; q < 4; q++) c[mt][nt][q] = 0.f;

    issue(0, 0); CP_COMMIT();
    issue(1, 1); CP_COMMIT();
    issue(2, 2); CP_COMMIT();

    for (int j = 0; j < NITER; j++) {
        CP_WAIT2();
        __syncthreads();

        if (j + 3 < NITER) issue((j + 3) & 3, j + 3);
        CP_COMMIT();

        const uint32_t sb = smb + (j & 3) * STG;
#pragma unroll
        for (int s = 0; s < 2; s++) {
            uint32_t af[4][4], bf[4][2];
#pragma unroll
            for (int mt = 0; mt < 4; mt++)
                ldsm4(af[mt], sb + aOff[mt] + s * 32);
#pragma unroll
            for (int p = 0; p < 2; p++) {
                uint32_t r[4];
                ldsm4(r, sb + bOff[p] + s * 32);
                bf[2 * p][0]     = r[0]; bf[2 * p][1]     = r[1];
                bf[2 * p + 1][0] = r[2]; bf[2 * p + 1][1] = r[3];
            }
#pragma unroll
            for (int mt = 0; mt < 4; mt++)
#pragma unroll
                for (int nt = 0; nt < 4; nt++)
                    mma16816(c[mt][nt], af[mt], bf[nt]);
        }
    }

    // epilogue: bias (+residual) fused
    const int rq = lane >> 2;
    const int cq = (lane & 3) * 2;
#pragma unroll
    for (int mt = 0; mt < 4; mt++) {
        const int r0 = bm + wm + mt * 16 + rq;
#pragma unroll
        for (int nt = 0; nt < 4; nt++) {
            const int col = colbase + wn + nt * 8 + cq;
            float2 bia = *(const float2*)(bias + col);
            float2 v0 = {c[mt][nt][0] + bia.x, c[mt][nt][1] + bia.y};
            float2 v1 = {c[mt][nt][2] + bia.x, c[mt][nt][3] + bia.y};
            if (!QKV && resid) {
                float2 e0 = *(const float2*)(resid + (size_t)r0 * 512 + col);
                float2 e1 = *(const float2*)(resid + (size_t)(r0 + 8) * 512 + col);
                v0.x += e0.x; v0.y += e0.y;
                v1.x += e1.x; v1.y += e1.y;
            }
            *(float2*)(C + (size_t)r0 * ldc + col)       = v0;
            *(float2*)(C + (size_t)(r0 + 8) * ldc + col) = v1;
        }
    }
}

// ---------------- attention: one block per (b, h), 64 threads ---------------
__global__ void __launch_bounds__(64)
attn_kernel(const void* __restrict__ maskp, const float* __restrict__ hyper,
            float* __restrict__ w_out)
{
    const int bh = blockIdx.x;
    const int b  = bh >> 4;
    const int h  = bh & 15;
    const int t  = threadIdx.x;

    __shared__ float qs[8][32], ks[8][32], vs[8][32], hy[8][32];
    __shared__ float sc[8][8], ws[8][8];

    const int base = (b * Ssz) * 1536 + h * 32;
    for (int idx = t; idx < 256; idx += 64) {
        const int i = idx >> 5, d = idx & 31;
        qs[i][d] = g_qkv[base + i * 1536 + d];
        ks[i][d] = g_qkv[base + i * 1536 + 512 + d];
        vs[i][d] = g_qkv[base + i * 1536 + 1024 + d];
        hy[i][d] = hyper[b * (Hsz * Ssz * 32) + h * (Ssz * 32) + i * 32 + d];
    }
    __syncthreads();

    const int i = t >> 3, j = t & 7;

    const int midx = b * 64 + i * 8 + j;
    const int mode = g_mask_mode;
    bool masked;
    if (mode == 0)      masked = ((const unsigned char*)maskp)[midx] != 0;
    else if (mode == 1) masked = ((const int*)maskp)[midx] != 0;
    else                masked = ((const float*)maskp)[midx] != 0.0f;

    float s;
    if (masked) {
        s = -1e9f;
    } else {
        float dot = 0.f;
#pragma unroll
        for (int d = 0; d < 32; d++) dot = fmaf(qs[i][d], ks[j][d], dot);
        s = dot * 0.17677669529663687f;   // 1/sqrt(32)
    }
    sc[i][j] = s;
    __syncthreads();

    float mx = sc[i][0];
#pragma unroll
    for (int jj = 1; jj < 8; jj++) mx = fmaxf(mx, sc[i][jj]);
    float sum = 0.f;
#pragma unroll
    for (int jj = 0; jj < 8; jj++) sum += expf(sc[i][jj] - mx);
    const float w = expf(s - mx) / sum;
    ws[i][j] = w;
    w_out[(size_t)bh * 64 + i * 8 + j] = w;
    __syncthreads();

    // context row i, 4 consecutive d; gate by hyper; emit [hi|lo] fp16 pair
    const int d0 = (t & 7) * 4;
    float c[4] = {};
#pragma unroll
    for (int jj = 0; jj < 8; jj++) {
        const float wv = ws[i][jj];
#pragma unroll
        for (int q = 0; q < 4; q++) c[q] = fmaf(wv, vs[jj][d0 + q], c[q]);
    }
    const int row = b * Ssz + i;
    const int k0  = h * 32 + d0;
    __half* rowp = g_actx + (size_t)row * KP;
    __half hi[4], lo[4];
#pragma unroll
    for (int q = 0; q < 4; q++) {
        const float val = c[q] * hy[i][d0 + q];
        hi[q] = __float2half_rn(val);
        lo[q] = __float2half_rn(val - __half2float(hi[q]));
    }
    *(__half2*)(rowp + k0)           = {hi[0], hi[1]};
    *(__half2*)(rowp + k0 + 2)       = {hi[2], hi[3]};
    *(__half2*)(rowp + 512 + k0)     = {lo[0], lo[1]};
    *(__half2*)(rowp + 512 + k0 + 2) = {lo[2], lo[3]};
}

// ---------------- layernorm: one warp per row of 512 ------------------------
__global__ void __launch_bounds__(256)
ln_kernel(const float* __restrict__ gamma, const float* __restrict__ beta,
          float* __restrict__ out)
{
    const int warp = (blockIdx.x * blockDim.x + threadIdx.x) >> 5;
    const int lane = threadIdx.x & 31;
    if (warp >= MROWS) return;
    const float* row = g_pre + (size_t)warp * Dsz;

    float x[16];
    float sum = 0.f, sumsq = 0.f;
#pragma unroll
    for (int i = 0; i < 16; i++) {
        x[i] = row[lane + i * 32];
        sum += x[i];
        sumsq = fmaf(x[i], x[i], sumsq);
    }
#pragma unroll
    for (int o = 16; o > 0; o >>= 1) {
        sum   += __shfl_xor_sync(0xFFFFFFFFu, sum, o);
        sumsq += __shfl_xor_sync(0xFFFFFFFFu, sumsq, o);
    }
    const float mu  = sum * (1.0f / 512.0f);
    const float var = sumsq * (1.0f / 512.0f) - mu * mu;
    const float rs  = rsqrtf(var + 1e-5f);
#pragma unroll
    for (int i = 0; i < 16; i++) {
        const int c = lane + i * 32;
        out[(size_t)warp * Dsz + c] = (x[i] - mu) * rs * gamma[c] + beta[c];
    }
}

// ---------------- launcher ---------------------------------------------------
extern "C" void kernel_launch(void* const* d_in, const int* in_sizes, int n_in,
                              void* d_out, int out_size)
{
    const float* Q     = (const float*)d_in[0];
    const float* K     = (const float*)d_in[1];
    const float* V     = (const float*)d_in[2];
    const void*  mask  = d_in[3];
    const float* hyper = (const float*)d_in[4];
    const float* Wq    = (const float*)d_in[5];
    const float* bq    = (const float*)d_in[6];
    const float* Wk    = (const float*)d_in[7];
    const float* bk    = (const float*)d_in[8];
    const float* Wv    = (const float*)d_in[9];
    const float* bv    = (const float*)d_in[10];
    const float* Wo    = (const float*)d_in[11];
    const float* bo    = (const float*)d_in[12];
    const float* ln_g  = (const float*)d_in[13];
    const float* ln_b  = (const float*)d_in[14];

    float* out   = (float*)d_out;
    float* w_out = out + (size_t)MROWS * Dsz;

    float *gqkv, *gpre, *gbqkv;
    __half *aq, *ak, *av, *actx, *wqkv, *wo;
    cudaGetSymbolAddress((void**)&gqkv,  g_qkv);
    cudaGetSymbolAddress((void**)&gpre,  g_pre);
    cudaGetSymbolAddress((void**)&gbqkv, g_bqkv);
    cudaGetSymbolAddress((void**)&aq,    g_aq);
    cudaGetSymbolAddress((void**)&ak,    g_ak);
    cudaGetSymbolAddress((void**)&av,    g_av);
    cudaGetSymbolAddress((void**)&actx,  g_actx);
    cudaGetSymbolAddress((void**)&wqkv,  g_wqkv);
    cudaGetSymbolAddress((void**)&wo,    g_wo);

    cudaFuncSetAttribute(gemm_mma<true>,  cudaFuncAttributeMaxDynamicSharedMemorySize, GEMM_SMEM);
    cudaFuncSetAttribute(gemm_mma<false>, cudaFuncAttributeMaxDynamicSharedMemorySize, GEMM_SMEM);

    // probes + converts
    detect_mask<<<1, 256>>>((const uint4*)mask);
    concat_bias<<<6, 256>>>(bq, bk, bv);
    split_a<<<dim3(4096, 1, 3), 256>>>(Q, K, V, aq, ak, av);
    conv_w<<<dim3(256, 1, 4), 256>>>(Wq, Wk, Wv, Wo);

    // merged QKV projection (one launch, 768 CTAs)
    gemm_mma<true><<<dim3(4, 64, 3), 256, GEMM_SMEM>>>(aq, ak, av, wqkv, gbqkv, nullptr, gqkv);

    // attention (emits weights + [hi|lo] fp16 gated context)
    attn_kernel<<<Bsz * Hsz, 64>>>(mask, hyper, w_out);

    // output projection with fused residual
    gemm_mma<false><<<dim3(4, 64), 256, GEMM_SMEM>>>(actx, nullptr, nullptr, wo, bo, Q, gpre);

    // layernorm
    ln_kernel<<<(MROWS * 32 + 255) / 256, 256>>>(ln_g, ln_b, out);
}